// round 5
// baseline (speedup 1.0000x reference)
#include <cuda_runtime.h>
#include <cuda_fp16.h>
#include <cstdint>
#include <cstddef>

// Problem dims (fixed)
#define BS_TOTAL 4096
#define D_DIM    1024
#define W_DIM    4096
#define NLEAF    8
#define C_DIM    11
#define SELP2    144    // per w-PAIR: 64 weights*2 interleaved + 8 biases*2

// ---------------- scratch (device globals) ----------------
__device__ float g_selp2[(W_DIM / 2) * SELP2];      // interleaved w-pairs
__device__ float g_slots[BS_TOTAL * 8];
__device__ __half g_rA[(size_t)W_DIM * BS_TOTAL];   // roots fp16, [k=w][m=bs]
__device__ __half g_wB[(size_t)W_DIM * D_DIM];      // out_w fp16, [k=w][n=d]

// ---------------- packed f32x2 helpers (sm_100-family base ISA) ------------
typedef unsigned long long u64b;
__device__ __forceinline__ u64b pack2(float a, float b) {
    u64b r;
    asm("mov.b64 %0, {%1, %2};" : "=l"(r) : "f"(a), "f"(b));
    return r;
}
__device__ __forceinline__ void unpack2(u64b v, float& a, float& b) {
    asm("mov.b64 {%0, %1}, %2;" : "=f"(a), "=f"(b) : "l"(v));
}
__device__ __forceinline__ u64b fma2(u64b a, u64b b, u64b c) {
    u64b d;
    asm("fma.rn.f32x2 %0, %1, %2, %3;" : "=l"(d) : "l"(a), "l"(b), "l"(c));
    return d;
}
__device__ __forceinline__ u64b mul2(u64b a, u64b b) {
    u64b d;
    asm("mul.rn.f32x2 %0, %1, %2;" : "=l"(d) : "l"(a), "l"(b));
    return d;
}

// tanh: 1 - 2/(exp(2x)+1) via ex2/rcp approx (~1e-6 abs err)
__device__ __forceinline__ float fast_tanh(float x) {
    float t = x * 2.885390081777926814f;
    float e;
    asm("ex2.approx.f32 %0, %1;" : "=f"(e) : "f"(t));
    float d = e + 1.0f;
    float r;
    asm("rcp.approx.f32 %0, %1;" : "=f"(r) : "f"(d));
    return fmaf(-2.0f, r, 1.0f);
}
__device__ __forceinline__ u64b tanh2(u64b x) {
    float a, b;
    unpack2(x, a, b);
    return pack2(fast_tanh(a), fast_tanh(b));
}

// ---------------- K1a: softmax -> interleaved w-pair selector ----------------
__global__ void k_sel(const float* __restrict__ logits) {
    int i = blockIdx.x * blockDim.x + threadIdx.x;   // (w*8 + l)
    if (i >= W_DIM * NLEAF) return;
    const float* p = logits + (size_t)i * C_DIM;
    float v[C_DIM];
#pragma unroll
    for (int c = 0; c < C_DIM; c++) v[c] = p[c];
    float m = v[0];
#pragma unroll
    for (int c = 1; c < C_DIM; c++) m = fmaxf(m, v[c]);
    float s = 0.0f;
#pragma unroll
    for (int c = 0; c < C_DIM; c++) { v[c] = __expf(v[c] - m); s += v[c]; }
    float r = 1.0f / s;
    int w = i >> 3, l = i & 7;
    int pr = w >> 1, q = w & 1;
    float* o = g_selp2 + (size_t)pr * SELP2;
#pragma unroll
    for (int c = 0; c < 8; c++) o[(l * 8 + c) * 2 + q] = v[c] * r;
    o[(64 + l) * 2 + q] = (v[10] - v[8]) * r;   // constants (-1,0,+1) folded
}

// ---------------- K1b: slots = tanh(hidden @ slot_w + slot_b) ----------------
__global__ void k_slots(const float* __restrict__ hidden,
                        const float* __restrict__ sw,
                        const float* __restrict__ sb) {
    int gwarp = (blockIdx.x * blockDim.x + threadIdx.x) >> 5;
    int lane = threadIdx.x & 31;
    if (gwarp >= BS_TOTAL) return;
    const float* h = hidden + (size_t)gwarp * D_DIM;
    float acc[8];
#pragma unroll
    for (int s = 0; s < 8; s++) acc[s] = 0.0f;
    for (int d0 = lane * 4; d0 < D_DIM; d0 += 128) {
        float4 hv = *(const float4*)(h + d0);
        const float* hvp = (const float*)&hv;
#pragma unroll
        for (int j = 0; j < 4; j++) {
            float hx = hvp[j];
            float4 w0 = *(const float4*)(sw + (size_t)(d0 + j) * 8);
            float4 w1 = *(const float4*)(sw + (size_t)(d0 + j) * 8 + 4);
            acc[0] = fmaf(hx, w0.x, acc[0]);
            acc[1] = fmaf(hx, w0.y, acc[1]);
            acc[2] = fmaf(hx, w0.z, acc[2]);
            acc[3] = fmaf(hx, w0.w, acc[3]);
            acc[4] = fmaf(hx, w1.x, acc[4]);
            acc[5] = fmaf(hx, w1.y, acc[5]);
            acc[6] = fmaf(hx, w1.z, acc[6]);
            acc[7] = fmaf(hx, w1.w, acc[7]);
        }
    }
#pragma unroll
    for (int off = 16; off > 0; off >>= 1) {
#pragma unroll
        for (int s = 0; s < 8; s++)
            acc[s] += __shfl_xor_sync(0xFFFFFFFFu, acc[s], off);
    }
    if (lane < 8)
        g_slots[(size_t)gwarp * 8 + lane] = fast_tanh(acc[lane] + sb[lane]);
}

// ---------------- K1c: out_w fp32 -> fp16 ([k][n], no transpose) ------------
__global__ void k_wconv(const float* __restrict__ ow) {
    int i = (blockIdx.x * blockDim.x + threadIdx.x) * 4;
    if (i >= W_DIM * D_DIM) return;
    float4 x = *(const float4*)(ow + i);
    __half2 a = __floats2half2_rn(x.x, x.y);
    __half2 b = __floats2half2_rn(x.z, x.w);
    *(__half2*)(g_wB + i) = a;
    *(__half2*)(g_wB + i + 2) = b;
}

// ---------------- K2: fused einsum + tanh tree, f32x2-packed w-pairs --------
// Block: 256 threads (1 bs each), 32 w-pairs (= 64 w). Grid 64 x 16.
#define K2_PAIRS 32
__global__ __launch_bounds__(256) void k_roots(const float* __restrict__ np) {
    __shared__ float s_sel[K2_PAIRS * SELP2];   // 18 KB

    int p0 = blockIdx.x * K2_PAIRS;            // pair base; w0 = 2*p0
    int bs = blockIdx.y * 256 + threadIdx.x;
    int tid = threadIdx.x;

    {
        const float4* src = (const float4*)(g_selp2 + (size_t)p0 * SELP2);
        float4* dst = (float4*)s_sel;
#pragma unroll
        for (int i = tid; i < K2_PAIRS * SELP2 / 4; i += 256) dst[i] = src[i];
    }

    float lw = np[0], rw = np[1], pw = np[2], dw = np[3], nb = np[4];
    u64b ca2 = pack2(lw + dw, lw + dw);
    u64b cb2 = pack2(rw - dw, rw - dw);
    u64b pw2 = pack2(pw, pw);
    u64b nb2 = pack2(nb, nb);

    float4 s01 = *(const float4*)(g_slots + (size_t)bs * 8);
    float4 s23 = *(const float4*)(g_slots + (size_t)bs * 8 + 4);
    u64b s2[8];
    s2[0] = pack2(s01.x, s01.x);
    s2[1] = pack2(s01.y, s01.y);
    s2[2] = pack2(s01.z, s01.z);
    s2[3] = pack2(s01.w, s01.w);
    s2[4] = pack2(s23.x, s23.x);
    s2[5] = pack2(s23.y, s23.y);
    s2[6] = pack2(s23.z, s23.z);
    s2[7] = pack2(s23.w, s23.w);

    __syncthreads();

    for (int pi = 0; pi < K2_PAIRS; pi++) {
        const u64b* sp = (const u64b*)(s_sel + pi * SELP2);
        u64b v[8];
#pragma unroll
        for (int l = 0; l < 8; l++) {
            u64b t = sp[64 + l];                 // packed bias
#pragma unroll
            for (int j = 0; j < 8; j++)
                t = fma2(sp[l * 8 + j], s2[j], t);
            v[l] = t;
        }
#pragma unroll
        for (int i = 0; i < 4; i++) {
            u64b L = v[2 * i], R = v[2 * i + 1];
            u64b u = fma2(ca2, L, nb2);
            u = fma2(cb2, R, u);
            u = fma2(pw2, mul2(L, R), u);
            v[i] = tanh2(u);
        }
#pragma unroll
        for (int i = 0; i < 2; i++) {
            u64b L = v[2 * i], R = v[2 * i + 1];
            u64b u = fma2(ca2, L, nb2);
            u = fma2(cb2, R, u);
            u = fma2(pw2, mul2(L, R), u);
            v[i] = tanh2(u);
        }
        u64b L = v[0], R = v[1];
        u64b u = fma2(ca2, L, nb2);
        u = fma2(cb2, R, u);
        u = fma2(pw2, mul2(L, R), u);
        float ra, rb;
        unpack2(u, ra, rb);
        ra = fast_tanh(ra);
        rb = fast_tanh(rb);

        size_t w = (size_t)(p0 + pi) * 2;
        g_rA[w * BS_TOTAL + bs] = __float2half(ra);
        g_rA[(w + 1) * BS_TOTAL + bs] = __float2half(rb);
    }
}

// ---------------- K3: C = roots @ out_w + out_b  (single fp16 product) ------
// BM=128, BN=128, BK=32; 8 warps (2m x 4n); 4-stage cp.async, 1 sync/iter.
#define BM 128
#define BN 128
#define BK 32
#define NKT (W_DIM / BK)     // 128
#define NSTAGE 4
#define SA_PITCH (BM + 8)    // halves
#define SB_PITCH (BN + 8)
#define STG_HALVES (BK * SA_PITCH + BK * SB_PITCH)
#define G_SMEM (NSTAGE * STG_HALVES * 2)

__device__ __forceinline__ uint32_t smem_u32(const void* p) {
    uint32_t a;
    asm("{ .reg .u64 t; cvta.to.shared.u64 t, %1; cvt.u32.u64 %0, t; }"
        : "=r"(a) : "l"(p));
    return a;
}
__device__ __forceinline__ void cp16(uint32_t dst, const void* src) {
    asm volatile("cp.async.cg.shared.global [%0], [%1], 16;"
                 :: "r"(dst), "l"(src));
}
#define CP_COMMIT() asm volatile("cp.async.commit_group;" ::: "memory")
#define CP_WAIT(N)  asm volatile("cp.async.wait_group %0;" :: "n"(N) : "memory")

#define LDMT(R0, R1, R2, R3, ADDR)                                          \
    asm volatile("ldmatrix.sync.aligned.m8n8.x4.trans.shared.b16 "          \
                 "{%0,%1,%2,%3}, [%4];"                                     \
                 : "=r"(R0), "=r"(R1), "=r"(R2), "=r"(R3) : "r"(ADDR))

#define MMA(C, A, B0, B1)                                                   \
    asm volatile("mma.sync.aligned.m16n8k16.row.col.f32.f16.f16.f32 "       \
                 "{%0,%1,%2,%3},{%4,%5,%6,%7},{%8,%9},{%0,%1,%2,%3};"       \
                 : "+f"(C[0]), "+f"(C[1]), "+f"(C[2]), "+f"(C[3])           \
                 : "r"(A[0]), "r"(A[1]), "r"(A[2]), "r"(A[3]),              \
                   "r"(B0), "r"(B1))

__global__ __launch_bounds__(256, 2) void k_gemm(const float* __restrict__ outb,
                                                 float* __restrict__ out) {
    extern __shared__ __half smem[];

    int tid = threadIdx.x;
    int wid = tid >> 5, lane = tid & 31;
    int wm = wid >> 2, wn = wid & 3;       // 2 x 4 warp grid
    int m0 = blockIdx.x * BM, n0 = blockIdx.y * BN;

    int ldrow = tid >> 4;        // 0..15 (+16)
    int ldcol = (tid & 15) * 8;  // halves

#define ISSUE_STAGE(ST, K0)                                                     \
    do {                                                                        \
        uint32_t sa = smem_u32(smem + (ST) * STG_HALVES);                       \
        uint32_t sbp = sa + BK * SA_PITCH * 2;                                  \
        _Pragma("unroll")                                                       \
        for (int i = 0; i < 2; i++) {                                           \
            int row = ldrow + i * 16;                                           \
            cp16(sa + (row * SA_PITCH + ldcol) * 2,                             \
                 g_rA + (size_t)((K0) + row) * BS_TOTAL + m0 + ldcol);          \
            cp16(sbp + (row * SB_PITCH + ldcol) * 2,                            \
                 g_wB + (size_t)((K0) + row) * D_DIM + n0 + ldcol);             \
        }                                                                       \
        CP_COMMIT();                                                            \
    } while (0)

    float acc[4][4][4];
#pragma unroll
    for (int a = 0; a < 4; a++)
#pragma unroll
        for (int b = 0; b < 4; b++)
#pragma unroll
            for (int c = 0; c < 4; c++) acc[a][b][c] = 0.0f;

    int kr = (lane & 7) | ((lane & 16) >> 1);
    int off8 = (lane & 8);

    ISSUE_STAGE(0, 0);
    ISSUE_STAGE(1, BK);
    ISSUE_STAGE(2, 2 * BK);

    for (int kt = 0; kt < NKT; kt++) {
        CP_WAIT(2);
        __syncthreads();
        // Safe: this sync separates compute(kt-1) (done by all warps) from the
        // overwrite of stage (kt+3)%4 == (kt-1)%4 below.
        if (kt + 3 < NKT) ISSUE_STAGE((kt + 3) % NSTAGE, (kt + 3) * BK);

        uint32_t sa = smem_u32(smem + (kt % NSTAGE) * STG_HALVES);
        uint32_t sbp = sa + BK * SA_PITCH * 2;

#pragma unroll
        for (int ks = 0; ks < 2; ks++) {
            uint32_t a[4][4], b[2][4];
#pragma unroll
            for (int mi = 0; mi < 4; mi++) {
                uint32_t moff =
                    ((ks * 16 + kr) * SA_PITCH + wm * 64 + mi * 16 + off8) * 2;
                LDMT(a[mi][0], a[mi][1], a[mi][2], a[mi][3], sa + moff);
            }
#pragma unroll
            for (int nj2 = 0; nj2 < 2; nj2++) {
                uint32_t noff =
                    ((ks * 16 + kr) * SB_PITCH + wn * 32 + nj2 * 16 + off8) * 2;
                LDMT(b[nj2][0], b[nj2][1], b[nj2][2], b[nj2][3], sbp + noff);
            }
#pragma unroll
            for (int mi = 0; mi < 4; mi++)
#pragma unroll
                for (int nj2 = 0; nj2 < 2; nj2++)
#pragma unroll
                    for (int h = 0; h < 2; h++)
                        MMA(acc[mi][nj2 * 2 + h], a[mi], b[nj2][h], b[nj2][h + 2]);
        }
    }

    // epilogue: += out_b, store fp32
    int g = lane >> 2;
    int t2 = (lane & 3) * 2;
#pragma unroll
    for (int mi = 0; mi < 4; mi++)
#pragma unroll
        for (int nj = 0; nj < 4; nj++) {
            int row = m0 + wm * 64 + mi * 16 + g;
            int col = n0 + wn * 32 + nj * 8 + t2;
            float b0 = outb[col];
            float b1 = outb[col + 1];
            float* p0 = out + (size_t)row * D_DIM + col;
            float* p1 = out + (size_t)(row + 8) * D_DIM + col;
            float2 v0 = {acc[mi][nj][0] + b0, acc[mi][nj][1] + b1};
            float2 v1 = {acc[mi][nj][2] + b0, acc[mi][nj][3] + b1};
            *(float2*)p0 = v0;
            *(float2*)p1 = v1;
        }
}

// ---------------- launch ----------------
extern "C" void kernel_launch(void* const* d_in, const int* in_sizes, int n_in,
                              void* d_out, int out_size) {
    const float* hidden = (const float*)d_in[0];
    const float* slot_w = (const float*)d_in[1];
    const float* slot_b = (const float*)d_in[2];
    const float* leaf_logits = (const float*)d_in[3];
    const float* node_params = (const float*)d_in[4];
    const float* out_w = (const float*)d_in[5];
    const float* out_b = (const float*)d_in[6];
    float* out = (float*)d_out;
    (void)in_sizes; (void)n_in; (void)out_size;

    cudaFuncSetAttribute(k_gemm, cudaFuncAttributeMaxDynamicSharedMemorySize, G_SMEM);

    k_sel<<<(W_DIM * NLEAF + 255) / 256, 256>>>(leaf_logits);
    k_slots<<<(BS_TOTAL * 32 + 255) / 256, 256>>>(hidden, slot_w, slot_b);
    k_wconv<<<(W_DIM * D_DIM / 4 + 255) / 256, 256>>>(out_w);
    k_roots<<<dim3(W_DIM / (2 * K2_PAIRS), BS_TOTAL / 256), 256>>>(node_params);
    k_gemm<<<dim3(BS_TOTAL / BM, D_DIM / BN), 256, G_SMEM>>>(out_b, out);
}